// round 3
// baseline (speedup 1.0000x reference)
#include <cuda_runtime.h>
#include <cuda_bf16.h>

// NVAR feature expansion:
//   X: (8, 4, 4096) f32  ->  out: (8, 4, 3996, 231) f32
//   features per (b,r,t): [1, tap_0..tap_9, 220 degree-3 monomials]
//   tap_k = X[b, r, t - (9-k)*2]   (t >= 100, so never out of range)
//   monomials: combinations_with_replacement(range(10), 3), lexicographic.

#define KTAPS   10
#define NMON    220
#define NF      231          // 1 + KTAPS + NMON
#define NT_IN   4096
#define TRANS   100
#define NT_OUT  (NT_IN - TRANS)   // 3996
#define PADL    18           // (KTAPS-1)*SKIP, SKIP=2
#define TILE_T  64
#define NTHREADS 256

__global__ __launch_bounds__(NTHREADS)
void nvar_kernel(const float* __restrict__ X, float* __restrict__ out) {
    __shared__ float    s_x[TILE_T + PADL];
    __shared__ unsigned s_mon[NMON];

    const int tid    = threadIdx.x;
    const int br     = blockIdx.y;                 // b*4 + r, 0..31
    const int t0_out = blockIdx.x * TILE_T;        // output-time tile base
    const int valid  = min(TILE_T, NT_OUT - t0_out);

    // ---- generate monomial offset table (packed 2i | 2j<<8 | 2k<<16) ----
    if (tid < NMON) {
        int rem = tid;
        int i = 0;
        int cnt = KTAPS * (KTAPS + 1) / 2;         // #pairs for i=0 -> 55
        while (rem >= cnt) { rem -= cnt; ++i; cnt = (KTAPS - i) * (KTAPS - i + 1) / 2; }
        int j = i;
        cnt = KTAPS - j;                           // #k for this j
        while (rem >= cnt) { rem -= cnt; ++j; cnt = KTAPS - j; }
        int k = j + rem;
        s_mon[tid] = (unsigned)(2 * i) | ((unsigned)(2 * j) << 8) | ((unsigned)(2 * k) << 16);
    }

    // ---- stage X tile: source times [TRANS + t0_out - PADL, TRANS + t0_out + valid) ----
    // min source index = 100 - 18 = 82 >= 0, max = 4095: always in-bounds.
    {
        const int src0 = TRANS + t0_out - PADL;
        const float* Xbr = X + (size_t)br * NT_IN;
        for (int s = tid; s < valid + PADL; s += NTHREADS)
            s_x[s] = Xbr[src0 + s];
    }
    __syncthreads();

    if (tid >= NF) return;                          // lanes 231..255 idle

    // thread tid owns feature column f = tid across the whole tile
    float* orow = out + ((size_t)br * NT_OUT + t0_out) * NF + tid;

    if (tid == 0) {
        #pragma unroll 4
        for (int tl = 0; tl < valid; ++tl)
            orow[(size_t)tl * NF] = 1.0f;
    } else if (tid <= KTAPS) {
        const int o = 2 * (tid - 1);
        #pragma unroll 4
        for (int tl = 0; tl < valid; ++tl)
            orow[(size_t)tl * NF] = s_x[tl + o];
    } else {
        const unsigned mm = s_mon[tid - (KTAPS + 1)];
        const int o0 = (int)(mm & 0xFFu);
        const int o1 = (int)((mm >> 8) & 0xFFu);
        const int o2 = (int)((mm >> 16) & 0xFFu);
        #pragma unroll 4
        for (int tl = 0; tl < valid; ++tl)
            orow[(size_t)tl * NF] = (s_x[tl + o0] * s_x[tl + o1]) * s_x[tl + o2];
    }
}

extern "C" void kernel_launch(void* const* d_in, const int* in_sizes, int n_in,
                              void* d_out, int out_size) {
    const float* X   = (const float*)d_in[0];
    float*       out = (float*)d_out;

    const int br_total = in_sizes[0] / NT_IN;       // 8*4 = 32
    dim3 grid((NT_OUT + TILE_T - 1) / TILE_T, br_total);
    nvar_kernel<<<grid, NTHREADS>>>(X, out);
}

// round 5
// speedup vs baseline: 1.1651x; 1.1651x over previous
#include <cuda_runtime.h>
#include <cuda_bf16.h>
#include <cstdint>

// NVAR feature expansion:
//   X: (8, 4, 4096) f32  ->  out: (8, 4, 3996, 231) f32
//   features per (b,r,t): [1, tap_0..tap_9, 220 degree-3 monomials (i<=j<=k)]
//   tap_k = X[b, r, t - (9-k)*2], t = tout + 100  (always in-bounds)

#define KTAPS   10
#define NMON    220
#define NF      231           // 1 + KTAPS + NMON
#define NT_IN   4096
#define TRANS   100
#define NT_OUT  (NT_IN - TRANS)   // 3996
#define PADL    18            // (KTAPS-1)*SKIP
#define TILE_T  32
#define NTHREADS 256
#define NGROUPS  8            // feature groups (one per warp-row of threads)

// Per-group feature ranges over [0, 231): groups 0..6 get 29, group 7 gets 28.
template <int G>
__device__ __forceinline__ void do_feats(const float (&x)[KTAPS], float* __restrict__ srow) {
    constexpr int LO = G * 29;
    constexpr int HI = (G == 7) ? NF : LO + 29;

    if (LO == 0) srow[0] = 1.0f;

    // taps: features 1..10
    #pragma unroll
    for (int t = 0; t < KTAPS; ++t)
        if (t + 1 >= LO && t + 1 < HI) srow[t + 1] = x[t];

    // monomials in lexicographic (a<=b<=c) order — matches
    // combinations_with_replacement; product order ((xa*xb)*xc) matches jnp.prod.
    int m = 0;
    #pragma unroll
    for (int a = 0; a < KTAPS; ++a) {
        #pragma unroll
        for (int b = a; b < KTAPS; ++b) {
            float xab = x[a] * x[b];   // DCE'd by compiler when no store in range
            #pragma unroll
            for (int c = b; c < KTAPS; ++c) {
                int f = 1 + KTAPS + m;
                if (f >= LO && f < HI) srow[f] = xab * x[c];
                ++m;
            }
        }
    }
}

__device__ __forceinline__ uint32_t smem_u32(const void* p) {
    uint32_t a;
    asm("{ .reg .u64 t; cvta.to.shared.u64 t, %1; cvt.u32.u64 %0, t; }" : "=r"(a) : "l"(p));
    return a;
}

__global__ __launch_bounds__(NTHREADS)
void nvar_kernel(const float* __restrict__ X, float* __restrict__ out) {
    __shared__ alignas(16) float s_out[TILE_T * NF];   // 29568 B, layout == global
    __shared__ float s_x[TILE_T + PADL];

    const int tid    = threadIdx.x;
    const int tl     = tid & (TILE_T - 1);         // time-step within tile
    const int g      = tid >> 5;                   // feature group (uniform per warp)
    const int br     = blockIdx.y;                 // b*4 + r, 0..31
    const int t0     = blockIdx.x * TILE_T;
    const int valid  = min(TILE_T, NT_OUT - t0);   // 32 or 28 (always mult of 4)

    // stage input slice [TRANS + t0 - PADL, TRANS + t0 + valid)
    {
        const int src0 = TRANS + t0 - PADL;        // >= 82, always in-bounds
        const float* Xbr = X + (size_t)br * NT_IN;
        if (tid < valid + PADL) s_x[tid] = Xbr[src0 + tid];
    }
    __syncthreads();

    if (tl < valid) {
        float x[KTAPS];
        #pragma unroll
        for (int t = 0; t < KTAPS; ++t) x[t] = s_x[tl + 2 * t];   // conflict-free LDS

        float* srow = s_out + tl * NF;             // stride 231 words -> all-distinct banks
        switch (g) {
            case 0: do_feats<0>(x, srow); break;
            case 1: do_feats<1>(x, srow); break;
            case 2: do_feats<2>(x, srow); break;
            case 3: do_feats<3>(x, srow); break;
            case 4: do_feats<4>(x, srow); break;
            case 5: do_feats<5>(x, srow); break;
            case 6: do_feats<6>(x, srow); break;
            default: do_feats<7>(x, srow); break;
        }
    }
    __syncthreads();

    // one bulk async copy shared -> global: valid*924 bytes, 16B-aligned both sides
    if (tid == 0) {
        float* gdst = out + ((size_t)br * NT_OUT + t0) * NF;
        uint32_t src = smem_u32(s_out);
        uint32_t nbytes = (uint32_t)valid * (NF * 4);
        asm volatile("fence.proxy.async.shared::cta;" ::: "memory");
        asm volatile("cp.async.bulk.global.shared::cta.bulk_group [%0], [%1], %2;"
                     :: "l"(gdst), "r"(src), "r"(nbytes) : "memory");
        asm volatile("cp.async.bulk.commit_group;" ::: "memory");
        asm volatile("cp.async.bulk.wait_group 0;" ::: "memory");
    }
}

extern "C" void kernel_launch(void* const* d_in, const int* in_sizes, int n_in,
                              void* d_out, int out_size) {
    const float* X   = (const float*)d_in[0];
    float*       out = (float*)d_out;

    const int br_total = in_sizes[0] / NT_IN;       // 32
    dim3 grid((NT_OUT + TILE_T - 1) / TILE_T, br_total);   // 125 x 32
    nvar_kernel<<<grid, NTHREADS>>>(X, out);
}